// round 3
// baseline (speedup 1.0000x reference)
#include <cuda_runtime.h>
#include <cuda_bf16.h>

#define BATCH      1024
#define CODE_LEN   65536
#define NTHREADS   512
#define NBLOCKS    (BATCH / 2)     /* 512 CTAs, 2 rows each -> single wave */
#define ITERS      ((CODE_LEN / 4) / NTHREADS)   /* 32 */
#define MARGIN_F   0.01f

// Scratch (device globals; no allocation allowed)
__device__ float g_row_hinged[BATCH];
__device__ unsigned int g_done_count;   // zero-init; reset by last block

__global__ __launch_bounds__(NTHREADS)
void mse_hinge_onewave_kernel(const float* __restrict__ z1,
                              const float* __restrict__ z2,
                              float* __restrict__ out) {
    const int row0 = blockIdx.x * 2;

    const float4* __restrict__ a0 =
        reinterpret_cast<const float4*>(z1 + (size_t)row0 * CODE_LEN);
    const float4* __restrict__ b0 =
        reinterpret_cast<const float4*>(z2 + (size_t)row0 * CODE_LEN);
    const float4* __restrict__ a1 = a0 + CODE_LEN / 4;
    const float4* __restrict__ b1 = b0 + CODE_LEN / 4;

    // Independent accumulator chains per row.
    float r0a = 0.0f, r0b = 0.0f;
    float r1a = 0.0f, r1b = 0.0f;

    #pragma unroll 4
    for (int i = 0; i < ITERS; ++i) {
        const int idx = threadIdx.x + i * NTHREADS;
        float4 va0 = a0[idx];
        float4 vb0 = b0[idx];
        float4 va1 = a1[idx];
        float4 vb1 = b1[idx];

        float d;
        d = va0.x - vb0.x; r0a = fmaf(d, d, r0a);
        d = va0.y - vb0.y; r0b = fmaf(d, d, r0b);
        d = va0.z - vb0.z; r0a = fmaf(d, d, r0a);
        d = va0.w - vb0.w; r0b = fmaf(d, d, r0b);

        d = va1.x - vb1.x; r1a = fmaf(d, d, r1a);
        d = va1.y - vb1.y; r1b = fmaf(d, d, r1b);
        d = va1.z - vb1.z; r1a = fmaf(d, d, r1a);
        d = va1.w - vb1.w; r1b = fmaf(d, d, r1b);
    }
    float acc0 = r0a + r0b;
    float acc1 = r1a + r1b;

    // Warp reduce both rows.
    #pragma unroll
    for (int o = 16; o > 0; o >>= 1) {
        acc0 += __shfl_xor_sync(0xffffffffu, acc0, o);
        acc1 += __shfl_xor_sync(0xffffffffu, acc1, o);
    }

    __shared__ float s_p0[NTHREADS / 32];
    __shared__ float s_p1[NTHREADS / 32];
    __shared__ bool  s_is_last;
    if ((threadIdx.x & 31) == 0) {
        s_p0[threadIdx.x >> 5] = acc0;
        s_p1[threadIdx.x >> 5] = acc1;
    }
    __syncthreads();

    if (threadIdx.x < 32) {
        float v0 = (threadIdx.x < NTHREADS / 32) ? s_p0[threadIdx.x] : 0.0f;
        float v1 = (threadIdx.x < NTHREADS / 32) ? s_p1[threadIdx.x] : 0.0f;
        #pragma unroll
        for (int o = 8; o > 0; o >>= 1) {
            v0 += __shfl_xor_sync(0xffffffffu, v0, o);
            v1 += __shfl_xor_sync(0xffffffffu, v1, o);
        }
        if (threadIdx.x == 0) {
            float mse0 = v0 * (1.0f / (float)CODE_LEN);
            float mse1 = v1 * (1.0f / (float)CODE_LEN);
            g_row_hinged[row0]     = (mse0 > MARGIN_F) ? (mse0 - MARGIN_F) : 0.0f;
            g_row_hinged[row0 + 1] = (mse1 > MARGIN_F) ? (mse1 - MARGIN_F) : 0.0f;
            __threadfence();
            unsigned int prev = atomicAdd(&g_done_count, 1u);
            s_is_last = (prev == NBLOCKS - 1);
        }
    }
    __syncthreads();

    // Last-arriving block: deterministic final reduction over 1024 row values.
    if (s_is_last) {
        if (threadIdx.x == 0)
            g_done_count = 0;   // reset for next graph replay

        float v = g_row_hinged[threadIdx.x] + g_row_hinged[threadIdx.x + NTHREADS];

        #pragma unroll
        for (int o = 16; o > 0; o >>= 1)
            v += __shfl_xor_sync(0xffffffffu, v, o);

        __shared__ float s_fin[NTHREADS / 32];
        if ((threadIdx.x & 31) == 0)
            s_fin[threadIdx.x >> 5] = v;
        __syncthreads();

        if (threadIdx.x < 32) {
            float w = (threadIdx.x < NTHREADS / 32) ? s_fin[threadIdx.x] : 0.0f;
            #pragma unroll
            for (int o = 8; o > 0; o >>= 1)
                w += __shfl_xor_sync(0xffffffffu, w, o);
            if (threadIdx.x == 0)
                out[0] = w * (1.0f / (float)BATCH);
        }
    }
}

extern "C" void kernel_launch(void* const* d_in, const int* in_sizes, int n_in,
                              void* d_out, int out_size) {
    const float* z1 = (const float*)d_in[0];
    const float* z2 = (const float*)d_in[1];
    float* out = (float*)d_out;

    mse_hinge_onewave_kernel<<<NBLOCKS, NTHREADS>>>(z1, z2, out);
}